// round 14
// baseline (speedup 1.0000x reference)
#include <cuda_runtime.h>
#include <cuda_fp16.h>
#include <math.h>
#include <stdint.h>

#define B_  2
#define S_  2048
#define D_  1024
#define H_  16
#define HD_ 64
#define M_  (B_*S_)   // 4096

// fp16 planes for the projection GEMM
__device__ __half g_Xf[M_*D_];          // X  [m][k]
__device__ __half g_Wf[3*D_*D_];        // W  [k][n] x3 (natural layout, fp16)
// Rotated Q/K/V single fp16 planes, [B,H,S,HD]. Q pre-scaled by 0.125*log2e.
__device__ __half g_Qf[B_*H_*S_*HD_];
__device__ __half g_Kf[B_*H_*S_*HD_];
__device__ __half g_Vf[B_*H_*S_*HD_];

// ===========================================================================
// helpers
// ===========================================================================
__device__ __forceinline__ uint32_t smem_u32(const void* p) {
    uint32_t a;
    asm("{ .reg .u64 t; cvta.to.shared.u64 t, %1; cvt.u32.u64 %0, t; }" : "=r"(a) : "l"(p));
    return a;
}
#define SWZ(off) ((off) ^ (((off) >> 3) & 0x70))

__device__ __forceinline__ void cpa16(uint32_t dst, const void* src) {
    asm volatile("cp.async.cg.shared.global [%0], [%1], 16;" :: "r"(dst), "l"(src));
}
#define CPA_COMMIT() asm volatile("cp.async.commit_group;" ::: "memory")
#define CPA_WAIT(n)  asm volatile("cp.async.wait_group %0;" :: "n"(n) : "memory")

__device__ __forceinline__ void ldm_x4(uint32_t& r0, uint32_t& r1, uint32_t& r2, uint32_t& r3, uint32_t a) {
    asm volatile("ldmatrix.sync.aligned.m8n8.x4.shared.b16 {%0,%1,%2,%3}, [%4];"
                 : "=r"(r0), "=r"(r1), "=r"(r2), "=r"(r3) : "r"(a));
}
__device__ __forceinline__ void ldm_x4t(uint32_t& r0, uint32_t& r1, uint32_t& r2, uint32_t& r3, uint32_t a) {
    asm volatile("ldmatrix.sync.aligned.m8n8.x4.trans.shared.b16 {%0,%1,%2,%3}, [%4];"
                 : "=r"(r0), "=r"(r1), "=r"(r2), "=r"(r3) : "r"(a));
}
// fp16 MMA
__device__ __forceinline__ void mma16816h(float* c, const uint32_t* a, uint32_t b0, uint32_t b1) {
    asm volatile(
        "mma.sync.aligned.m16n8k16.row.col.f32.f16.f16.f32 "
        "{%0,%1,%2,%3}, {%4,%5,%6,%7}, {%8,%9}, {%0,%1,%2,%3};"
        : "+f"(c[0]), "+f"(c[1]), "+f"(c[2]), "+f"(c[3])
        : "r"(a[0]), "r"(a[1]), "r"(a[2]), "r"(a[3]), "r"(b0), "r"(b1));
}
// fp16 pack
__device__ __forceinline__ uint32_t packh(float p0, float p1) {
    uint32_t r;
    asm("cvt.rn.f16x2.f32 %0, %1, %2;" : "=r"(r) : "f"(p1), "f"(p0));
    return r;
}
__device__ __forceinline__ float ex2(float x) {
    float y; asm("ex2.approx.f32 %0, %1;" : "=f"(y) : "f"(x)); return y;
}

// ===========================================================================
// Prep kernels: streaming fp32 -> fp16 packs (no transpose).
// ===========================================================================
__global__ __launch_bounds__(256) void prep_x_kernel(const float* __restrict__ X)
{
    const int i = blockIdx.x * 256 + threadIdx.x;     // float4 index, 1M total
    float4 v = ((const float4*)X)[i];
    ((uint32_t*)g_Xf)[i*2]   = packh(v.x, v.y);
    ((uint32_t*)g_Xf)[i*2+1] = packh(v.z, v.w);
}

__global__ __launch_bounds__(256) void prep_w_kernel(
    const float* __restrict__ Wq, const float* __restrict__ Wk, const float* __restrict__ Wv)
{
    const int i = blockIdx.x * 256 + threadIdx.x;     // 0 .. 768K-1
    const int w = i >> 18;                            // 256K float4 per W
    const int j = i & 0x3FFFF;
    const float* W = (w == 0) ? Wq : (w == 1 ? Wk : Wv);
    float4 v = ((const float4*)W)[j];
    uint32_t* O = (uint32_t*)(g_Wf + (size_t)w * D_ * D_);
    O[j*2]   = packh(v.x, v.y);
    O[j*2+1] = packh(v.z, v.w);
}

// ===========================================================================
// Kernel 1: QKV GEMM, fp16, tile 128x128, BK=64, cp.async 2-stage.
//   (unchanged from R13)
// ===========================================================================
#define QKV_STAGE 32768
#define QKV_SMEM (2 * QKV_STAGE)
#define LOG2E 1.44269504088896340736f

__global__ __launch_bounds__(256, 2)
void qkv_hmma_kernel(const float* __restrict__ sinT, const float* __restrict__ cosT)
{
    extern __shared__ char smem[];
    const uint32_t sbase = smem_u32(smem);
    const int tid = threadIdx.x;
    const int wid = tid >> 5;
    const int lane = tid & 31;
    const int wm = (wid >> 1) * 32;    // 0,32,64,96
    const int wp = (wid & 1);          // B plane 0/1 -> n offset 0/64

    const int which = blockIdx.z;
    const int bm = blockIdx.y * 128;
    const int bn = blockIdx.x * 128;
    const __half* Wp = g_Wf + (size_t)which * D_ * D_;
    __half* Outp = (which == 0) ? g_Qf : (which == 1 ? g_Kf : g_Vf);
    const float qscale = (which == 0) ? (0.125f * LOG2E) : 1.0f;

    auto issue = [&](int ch, int st) {
        const uint32_t sb = sbase + st * QKV_STAGE;
        #pragma unroll
        for (int it = 0; it < 4; it++) {
            const int idx = it * 256 + tid;
            const int row = idx >> 3, ck = idx & 7;
            cpa16(sb + SWZ((uint32_t)(row * 128 + ck * 16)),
                  g_Xf + (size_t)(bm + row) * D_ + ch * 64 + ck * 8);
        }
        #pragma unroll
        for (int p = 0; p < 2; p++) {
            #pragma unroll
            for (int it = 0; it < 2; it++) {
                const int idx = it * 256 + tid;
                const int row = idx >> 3, ck = idx & 7;
                cpa16(sb + 16384 + p * 8192 + SWZ((uint32_t)(row * 128 + ck * 16)),
                      Wp + (size_t)(ch * 64 + row) * D_ + bn + p * 64 + ck * 8);
            }
        }
        CPA_COMMIT();
    };

    float acc[2][8][4];
    #pragma unroll
    for (int i = 0; i < 2; i++)
        #pragma unroll
        for (int j = 0; j < 8; j++)
            #pragma unroll
            for (int k = 0; k < 4; k++) acc[i][j][k] = 0.f;

    issue(0, 0); issue(1, 1);

    for (int ch = 0; ch < 16; ch++) {
        if (ch < 15) { CPA_WAIT(1); } else { CPA_WAIT(0); }
        __syncthreads();

        const int st = ch & 1;
        const uint32_t sA = sbase + st * QKV_STAGE;
        const uint32_t sB = sA + 16384 + wp * 8192;

        #pragma unroll
        for (int ks = 0; ks < 4; ks++) {
            uint32_t af[2][4];
            #pragma unroll
            for (int mt = 0; mt < 2; mt++) {
                const int row = wm + mt * 16 + (lane & 15);
                const uint32_t byt = (uint32_t)(row * 128 + ks * 32 + ((lane >> 4) << 4));
                ldm_x4(af[mt][0], af[mt][1], af[mt][2], af[mt][3], sA + SWZ(byt));
            }
            #pragma unroll
            for (int ntq = 0; ntq < 4; ntq++) {
                const int row = ks * 16 + (lane & 15);
                const uint32_t byt = (uint32_t)(row * 128 + ntq * 32 + ((lane >> 4) << 4));
                uint32_t b0, b1, b2, b3;
                ldm_x4t(b0, b1, b2, b3, sB + SWZ(byt));
                #pragma unroll
                for (int mt = 0; mt < 2; mt++) {
                    mma16816h(acc[mt][2*ntq],   af[mt], b0, b1);
                    mma16816h(acc[mt][2*ntq+1], af[mt], b2, b3);
                }
            }
        }
        __syncthreads();
        if (ch + 2 < 16) issue(ch + 2, st);
    }

    // epilogue: RoPE + scale, pack to single fp16 plane
    const int g = lane >> 2;
    const int q2 = (lane & 3) * 2;
    #pragma unroll
    for (int mt = 0; mt < 2; mt++) {
        #pragma unroll
        for (int rr = 0; rr < 2; rr++) {
            const int row = bm + wm + mt * 16 + g + rr * 8;
            const int bb = row >> 11;
            const int ss = row & 2047;
            #pragma unroll
            for (int nt = 0; nt < 8; nt++) {
                const int c = bn + wp * 64 + nt * 8 + q2;
                const int h = c >> 6;
                const int d = c & 63;
                const float sn = sinT[ss * (HD_/2) + (d >> 1)];
                const float cs = cosT[ss * (HD_/2) + (d >> 1)];
                const float e = acc[mt][nt][rr * 2 + 0];
                const float o = acc[mt][nt][rr * 2 + 1];
                const float wx = (e * cs - o * sn) * qscale;
                const float wy = (o * cs + e * sn) * qscale;
                const size_t ob = ((size_t)(bb * H_ + h) * S_ + ss) * HD_ + d;
                *(uint32_t*)&Outp[ob] = packh(wx, wy);
            }
        }
    }
}

// ===========================================================================
// Kernel 2: flash attention, fp16 single-plane, fused softmax+PV chunks.
//   BQ=128 (8 warps x 16 rows), kt tiles of 64, 2-stage KV pipeline.
//   Per k-chunk: 8 ex2 -> 4 packh -> 8 PV MMAs + 1 ones-MMA (l row-sum),
//   so MUFU (ex2) overlaps tensor (prev chunk's MMAs). l needs no shuffles.
// smem: Qf 16KB + 2 x {Kf 8KB, Vf 8KB} = 48KB -> 2 CTAs/SM
// ===========================================================================
#define ATT_SMEM (16384 + 2 * 16384)
#define ONES2 0x3C003C00u    // fp16x2 (1.0, 1.0)

__global__ __launch_bounds__(256, 2)
void attn_hmma_kernel(float* __restrict__ Out)
{
    extern __shared__ char smem[];
    const uint32_t sbase = smem_u32(smem);
    const int tid = threadIdx.x;
    const int wid = tid >> 5;
    const int lane = tid & 31;
    const int g = lane >> 2;
    const int q2 = (lane & 3) * 2;

    const int q0 = blockIdx.x * 128;
    const int h  = blockIdx.y;
    const int b  = blockIdx.z;
    const size_t hoff = (size_t)(b * H_ + h) * S_ * HD_;
    const __half* Qfp = g_Qf + hoff;
    const __half* Kfp = g_Kf + hoff;
    const __half* Vfp = g_Vf + hoff;

    auto issueKV = [&](int kt, int st) {
        const uint32_t sb = sbase + 16384 + st * 16384;
        #pragma unroll
        for (int p = 0; p < 2; p++) {
            const __half* src = p ? Vfp : Kfp;
            #pragma unroll
            for (int it = 0; it < 2; it++) {
                const int idx = it * 256 + tid;    // 512 per plane
                const int row = idx >> 3, ck = idx & 7;
                cpa16(sb + p * 8192 + SWZ((uint32_t)(row * 128 + ck * 16)),
                      src + (size_t)(kt * 64 + row) * HD_ + ck * 8);
            }
        }
        CPA_COMMIT();
    };

    // prologue: Q (single plane) + KV 0,1
    #pragma unroll
    for (int it = 0; it < 4; it++) {
        const int idx = it * 256 + tid;
        const int row = idx >> 3, ck = idx & 7;
        cpa16(sbase + SWZ((uint32_t)(row * 128 + ck * 16)),
              Qfp + (size_t)(q0 + row) * HD_ + ck * 8);
    }
    CPA_COMMIT();
    issueKV(0, 0); issueKV(1, 1);

    CPA_WAIT(2);           // Q done
    __syncthreads();

    // Q fragments (held in registers for whole kernel)
    uint32_t qf[4][4];
    #pragma unroll
    for (int ks = 0; ks < 4; ks++) {
        const int row = wid * 16 + (lane & 15);
        const uint32_t byt = (uint32_t)(row * 128 + ks * 32 + ((lane >> 4) << 4));
        ldm_x4(qf[ks][0], qf[ks][1], qf[ks][2], qf[ks][3], sbase + SWZ(byt));
    }

    // l_acc: ones-MMA accumulator. l_acc[0]/[1] = row g sum (cols equal),
    // l_acc[2]/[3] = row g+8 sum. Accumulates across all tiles.
    float l_acc[4] = {0.f, 0.f, 0.f, 0.f};
    float o_acc[8][4];
    #pragma unroll
    for (int i = 0; i < 8; i++)
        #pragma unroll
        for (int j = 0; j < 4; j++) o_acc[i][j] = 0.f;

    for (int kt = 0; kt < 32; kt++) {
        if (kt < 31) { CPA_WAIT(1); } else { CPA_WAIT(0); }
        __syncthreads();

        const int st = kt & 1;
        const uint32_t sKf = sbase + 16384 + st * 16384;
        const uint32_t sVf = sKf + 8192;

        // ---- S = Q K^T (log2-domain scores) ----
        float sc[8][4];
        #pragma unroll
        for (int i = 0; i < 8; i++)
            #pragma unroll
            for (int j = 0; j < 4; j++) sc[i][j] = 0.f;

        #pragma unroll
        for (int ks = 0; ks < 4; ks++) {
            #pragma unroll
            for (int ntp = 0; ntp < 4; ntp++) {
                const int row = ntp * 16 + (lane & 15);
                const uint32_t byt = (uint32_t)(row * 128 + ks * 32 + ((lane >> 4) << 4));
                uint32_t h0,h1,h2,h3;
                ldm_x4(h0, h1, h2, h3, sKf + SWZ(byt));
                mma16816h(sc[2*ntp],   qf[ks], h0, h2);
                mma16816h(sc[2*ntp+1], qf[ks], h1, h3);
            }
        }

        // ---- fused softmax + PV per k-chunk: ex2 (MUFU) overlaps MMAs ----
        #pragma unroll
        for (int ks2 = 0; ks2 < 4; ks2++) {
            const int n0 = 2 * ks2, n1 = 2 * ks2 + 1;
            const float p00 = ex2(sc[n0][0]);
            const float p01 = ex2(sc[n0][1]);
            const float p02 = ex2(sc[n0][2]);
            const float p03 = ex2(sc[n0][3]);
            const float p10 = ex2(sc[n1][0]);
            const float p11 = ex2(sc[n1][1]);
            const float p12 = ex2(sc[n1][2]);
            const float p13 = ex2(sc[n1][3]);
            uint32_t aPf[4];
            aPf[0] = packh(p00, p01);
            aPf[1] = packh(p02, p03);
            aPf[2] = packh(p10, p11);
            aPf[3] = packh(p12, p13);
            // l row-sum via ones-column MMA (consistent with fp16 P weights)
            mma16816h(l_acc, aPf, ONES2, ONES2);
            #pragma unroll
            for (int dtp = 0; dtp < 4; dtp++) {
                const int row = ks2 * 16 + (lane & 15);
                const uint32_t byt = (uint32_t)(row * 128 + dtp * 32 + ((lane >> 4) << 4));
                uint32_t vh0,vh1,vh2,vh3;
                ldm_x4t(vh0, vh1, vh2, vh3, sVf + SWZ(byt));
                mma16816h(o_acc[2*dtp],   aPf, vh0, vh1);
                mma16816h(o_acc[2*dtp+1], aPf, vh2, vh3);
            }
        }
        __syncthreads();
        if (kt + 2 < 32) issueKV(kt + 2, st);
    }

    // ---- epilogue: l already full row-sum in every lane; no shuffles ----
    #pragma unroll
    for (int tr = 0; tr < 2; tr++) {
        const float inv = 1.f / l_acc[tr * 2];
        const int qrow = q0 + wid * 16 + g + tr * 8;
        #pragma unroll
        for (int dt = 0; dt < 8; dt++) {
            float2 w;
            w.x = o_acc[dt][tr*2]   * inv;
            w.y = o_acc[dt][tr*2+1] * inv;
            *(float2*)&Out[((size_t)b * S_ + qrow) * D_ + h * HD_ + dt * 8 + q2] = w;
        }
    }
}

// ---------------------------------------------------------------------------
extern "C" void kernel_launch(void* const* d_in, const int* in_sizes, int n_in,
                              void* d_out, int out_size)
{
    const float* X  = (const float*)d_in[0];
    const float* Wq = (const float*)d_in[1];
    const float* Wk = (const float*)d_in[2];
    const float* Wv = (const float*)d_in[3];
    const float* sn = (const float*)d_in[4];
    const float* cs = (const float*)d_in[5];
    float* out = (float*)d_out;

    prep_x_kernel<<<M_ * D_ / 4 / 256, 256>>>(X);               // 4096 blocks
    prep_w_kernel<<<3 * D_ * D_ / 4 / 256, 256>>>(Wq, Wk, Wv);  // 3072 blocks

    cudaFuncSetAttribute(qkv_hmma_kernel, cudaFuncAttributeMaxDynamicSharedMemorySize, QKV_SMEM);
    dim3 g1(D_ / 128, M_ / 128, 3);   // (8, 32, 3)
    qkv_hmma_kernel<<<g1, 256, QKV_SMEM>>>(sn, cs);

    cudaFuncSetAttribute(attn_hmma_kernel, cudaFuncAttributeMaxDynamicSharedMemorySize, ATT_SMEM);
    dim3 g2(S_ / 128, H_, B_);        // (16, 16, 2)
    attn_hmma_kernel<<<g2, 256, ATT_SMEM>>>(out);
}

// round 15
// speedup vs baseline: 1.0294x; 1.0294x over previous
#include <cuda_runtime.h>
#include <cuda_fp16.h>
#include <math.h>
#include <stdint.h>

#define B_  2
#define S_  2048
#define D_  1024
#define H_  16
#define HD_ 64
#define M_  (B_*S_)   // 4096

// fp16 planes for the projection GEMM
__device__ __half g_Xf[M_*D_];          // X  [m][k]
__device__ __half g_Wf[3*D_*D_];        // W  [k][n] x3 (natural layout, fp16)
// Rotated Q/K/V single fp16 planes, [B,H,S,HD]. Q pre-scaled by 0.125*log2e.
__device__ __half g_Qf[B_*H_*S_*HD_];
__device__ __half g_Kf[B_*H_*S_*HD_];
__device__ __half g_Vf[B_*H_*S_*HD_];

// ===========================================================================
// helpers
// ===========================================================================
__device__ __forceinline__ uint32_t smem_u32(const void* p) {
    uint32_t a;
    asm("{ .reg .u64 t; cvta.to.shared.u64 t, %1; cvt.u32.u64 %0, t; }" : "=r"(a) : "l"(p));
    return a;
}
#define SWZ(off) ((off) ^ (((off) >> 3) & 0x70))

__device__ __forceinline__ void cpa16(uint32_t dst, const void* src) {
    asm volatile("cp.async.cg.shared.global [%0], [%1], 16;" :: "r"(dst), "l"(src));
}
#define CPA_COMMIT() asm volatile("cp.async.commit_group;" ::: "memory")
#define CPA_WAIT(n)  asm volatile("cp.async.wait_group %0;" :: "n"(n) : "memory")

__device__ __forceinline__ void ldm_x4(uint32_t& r0, uint32_t& r1, uint32_t& r2, uint32_t& r3, uint32_t a) {
    asm volatile("ldmatrix.sync.aligned.m8n8.x4.shared.b16 {%0,%1,%2,%3}, [%4];"
                 : "=r"(r0), "=r"(r1), "=r"(r2), "=r"(r3) : "r"(a));
}
__device__ __forceinline__ void ldm_x4t(uint32_t& r0, uint32_t& r1, uint32_t& r2, uint32_t& r3, uint32_t a) {
    asm volatile("ldmatrix.sync.aligned.m8n8.x4.trans.shared.b16 {%0,%1,%2,%3}, [%4];"
                 : "=r"(r0), "=r"(r1), "=r"(r2), "=r"(r3) : "r"(a));
}
// fp16 MMA
__device__ __forceinline__ void mma16816h(float* c, const uint32_t* a, uint32_t b0, uint32_t b1) {
    asm volatile(
        "mma.sync.aligned.m16n8k16.row.col.f32.f16.f16.f32 "
        "{%0,%1,%2,%3}, {%4,%5,%6,%7}, {%8,%9}, {%0,%1,%2,%3};"
        : "+f"(c[0]), "+f"(c[1]), "+f"(c[2]), "+f"(c[3])
        : "r"(a[0]), "r"(a[1]), "r"(a[2]), "r"(a[3]), "r"(b0), "r"(b1));
}
// fp16 pack
__device__ __forceinline__ uint32_t packh(float p0, float p1) {
    uint32_t r;
    asm("cvt.rn.f16x2.f32 %0, %1, %2;" : "=r"(r) : "f"(p1), "f"(p0));
    return r;
}
__device__ __forceinline__ float ex2(float x) {
    float y; asm("ex2.approx.f32 %0, %1;" : "=f"(y) : "f"(x)); return y;
}

// ===========================================================================
// Prep: single merged kernel. Blocks [0,4096) pack X; [4096,7168) pack Ws.
// ===========================================================================
__global__ __launch_bounds__(256) void prep_kernel(
    const float* __restrict__ X,
    const float* __restrict__ Wq, const float* __restrict__ Wk, const float* __restrict__ Wv)
{
    const int blk = blockIdx.x;
    if (blk < 4096) {
        const int i = blk * 256 + threadIdx.x;            // float4 index, 1M total
        float4 v = ((const float4*)X)[i];
        ((uint32_t*)g_Xf)[i*2]   = packh(v.x, v.y);
        ((uint32_t*)g_Xf)[i*2+1] = packh(v.z, v.w);
    } else {
        const int i = (blk - 4096) * 256 + threadIdx.x;   // 0 .. 768K-1
        const int w = i >> 18;                            // 256K float4 per W
        const int j = i & 0x3FFFF;
        const float* W = (w == 0) ? Wq : (w == 1 ? Wk : Wv);
        float4 v = ((const float4*)W)[j];
        uint32_t* O = (uint32_t*)(g_Wf + (size_t)w * D_ * D_);
        O[j*2]   = packh(v.x, v.y);
        O[j*2+1] = packh(v.z, v.w);
    }
}

// ===========================================================================
// Kernel 1: QKV GEMM, fp16, tile 128x128, BK=64, cp.async 2-stage.
//   Batched ldmatrix: per ks chunk, all B ldms issued before the MMA group.
// ===========================================================================
#define QKV_STAGE 32768
#define QKV_SMEM (2 * QKV_STAGE)
#define LOG2E 1.44269504088896340736f

__global__ __launch_bounds__(256, 2)
void qkv_hmma_kernel(const float* __restrict__ sinT, const float* __restrict__ cosT)
{
    extern __shared__ char smem[];
    const uint32_t sbase = smem_u32(smem);
    const int tid = threadIdx.x;
    const int wid = tid >> 5;
    const int lane = tid & 31;
    const int wm = (wid >> 1) * 32;    // 0,32,64,96
    const int wp = (wid & 1);          // B plane 0/1 -> n offset 0/64

    const int which = blockIdx.z;
    const int bm = blockIdx.y * 128;
    const int bn = blockIdx.x * 128;
    const __half* Wp = g_Wf + (size_t)which * D_ * D_;
    __half* Outp = (which == 0) ? g_Qf : (which == 1 ? g_Kf : g_Vf);
    const float qscale = (which == 0) ? (0.125f * LOG2E) : 1.0f;

    // precomputed per-thread load offsets (invariant across chunks)
    uint32_t a_dst[4]; const __half* a_src[4];
    #pragma unroll
    for (int it = 0; it < 4; it++) {
        const int idx = it * 256 + tid;
        const int row = idx >> 3, ck = idx & 7;
        a_dst[it] = SWZ((uint32_t)(row * 128 + ck * 16));
        a_src[it] = g_Xf + (size_t)(bm + row) * D_ + ck * 8;
    }
    uint32_t b_dst[2][2]; const __half* b_src[2][2];
    #pragma unroll
    for (int p = 0; p < 2; p++)
        #pragma unroll
        for (int it = 0; it < 2; it++) {
            const int idx = it * 256 + tid;
            const int row = idx >> 3, ck = idx & 7;
            b_dst[p][it] = 16384 + p * 8192 + SWZ((uint32_t)(row * 128 + ck * 16));
            b_src[p][it] = Wp + (size_t)row * D_ + bn + p * 64 + ck * 8;
        }

    auto issue = [&](int ch, int st) {
        const uint32_t sb = sbase + st * QKV_STAGE;
        #pragma unroll
        for (int it = 0; it < 4; it++)
            cpa16(sb + a_dst[it], a_src[it] + ch * 64);
        #pragma unroll
        for (int p = 0; p < 2; p++)
            #pragma unroll
            for (int it = 0; it < 2; it++)
                cpa16(sb + b_dst[p][it], b_src[p][it] + (size_t)(ch * 64) * D_);
        CPA_COMMIT();
    };

    float acc[2][8][4];
    #pragma unroll
    for (int i = 0; i < 2; i++)
        #pragma unroll
        for (int j = 0; j < 8; j++)
            #pragma unroll
            for (int k = 0; k < 4; k++) acc[i][j][k] = 0.f;

    issue(0, 0); issue(1, 1);

    for (int ch = 0; ch < 16; ch++) {
        if (ch < 15) { CPA_WAIT(1); } else { CPA_WAIT(0); }
        __syncthreads();

        const int st = ch & 1;
        const uint32_t sA = sbase + st * QKV_STAGE;
        const uint32_t sB = sA + 16384 + wp * 8192;

        #pragma unroll
        for (int ks = 0; ks < 4; ks++) {
            // batch all ldmatrix for this ks before MMAs
            uint32_t af[2][4];
            #pragma unroll
            for (int mt = 0; mt < 2; mt++) {
                const int row = wm + mt * 16 + (lane & 15);
                const uint32_t byt = (uint32_t)(row * 128 + ks * 32 + ((lane >> 4) << 4));
                ldm_x4(af[mt][0], af[mt][1], af[mt][2], af[mt][3], sA + SWZ(byt));
            }
            uint32_t bf[4][4];
            #pragma unroll
            for (int ntq = 0; ntq < 4; ntq++) {
                const int row = ks * 16 + (lane & 15);
                const uint32_t byt = (uint32_t)(row * 128 + ntq * 32 + ((lane >> 4) << 4));
                ldm_x4t(bf[ntq][0], bf[ntq][1], bf[ntq][2], bf[ntq][3], sB + SWZ(byt));
            }
            #pragma unroll
            for (int ntq = 0; ntq < 4; ntq++)
                #pragma unroll
                for (int mt = 0; mt < 2; mt++) {
                    mma16816h(acc[mt][2*ntq],   af[mt], bf[ntq][0], bf[ntq][1]);
                    mma16816h(acc[mt][2*ntq+1], af[mt], bf[ntq][2], bf[ntq][3]);
                }
        }
        __syncthreads();
        if (ch + 2 < 16) issue(ch + 2, st);
    }

    // epilogue: RoPE + scale, pack to single fp16 plane
    const int g = lane >> 2;
    const int q2 = (lane & 3) * 2;
    #pragma unroll
    for (int mt = 0; mt < 2; mt++) {
        #pragma unroll
        for (int rr = 0; rr < 2; rr++) {
            const int row = bm + wm + mt * 16 + g + rr * 8;
            const int bb = row >> 11;
            const int ss = row & 2047;
            #pragma unroll
            for (int nt = 0; nt < 8; nt++) {
                const int c = bn + wp * 64 + nt * 8 + q2;
                const int h = c >> 6;
                const int d = c & 63;
                const float sn = sinT[ss * (HD_/2) + (d >> 1)];
                const float cs = cosT[ss * (HD_/2) + (d >> 1)];
                const float e = acc[mt][nt][rr * 2 + 0];
                const float o = acc[mt][nt][rr * 2 + 1];
                const float wx = (e * cs - o * sn) * qscale;
                const float wy = (o * cs + e * sn) * qscale;
                const size_t ob = ((size_t)(bb * H_ + h) * S_ + ss) * HD_ + d;
                *(uint32_t*)&Outp[ob] = packh(wx, wy);
            }
        }
    }
}

// ===========================================================================
// Kernel 2: flash attention, fp16 single-plane, fused softmax+PV,
//   batched ldmatrix groups, hoisted cp.async addressing.
// smem: Qf 16KB + 2 x {Kf 8KB, Vf 8KB} = 48KB -> 2 CTAs/SM
// ===========================================================================
#define ATT_SMEM (16384 + 2 * 16384)
#define ONES2 0x3C003C00u    // fp16x2 (1.0, 1.0)

__global__ __launch_bounds__(256, 2)
void attn_hmma_kernel(float* __restrict__ Out)
{
    extern __shared__ char smem[];
    const uint32_t sbase = smem_u32(smem);
    const int tid = threadIdx.x;
    const int wid = tid >> 5;
    const int lane = tid & 31;
    const int g = lane >> 2;
    const int q2 = (lane & 3) * 2;

    const int q0 = blockIdx.x * 128;
    const int h  = blockIdx.y;
    const int b  = blockIdx.z;
    const size_t hoff = (size_t)(b * H_ + h) * S_ * HD_;
    const __half* Qfp = g_Qf + hoff;

    // precomputed per-thread KV load offsets
    uint32_t kv_dst[2][2]; const __half* kv_src[2][2];
    {
        const __half* planes[2] = {g_Kf + hoff, g_Vf + hoff};
        #pragma unroll
        for (int p = 0; p < 2; p++)
            #pragma unroll
            for (int it = 0; it < 2; it++) {
                const int idx = it * 256 + tid;    // 512 per plane
                const int row = idx >> 3, ck = idx & 7;
                kv_dst[p][it] = 16384 + p * 8192 + SWZ((uint32_t)(row * 128 + ck * 16));
                kv_src[p][it] = planes[p] + (size_t)row * HD_ + ck * 8;
            }
    }

    auto issueKV = [&](int kt, int st) {
        const uint32_t sb = sbase + st * 16384;
        const int roff = kt * 64 * HD_;
        #pragma unroll
        for (int p = 0; p < 2; p++)
            #pragma unroll
            for (int it = 0; it < 2; it++)
                cpa16(sb + kv_dst[p][it], kv_src[p][it] + roff);
        CPA_COMMIT();
    };

    // prologue: Q (single plane) + KV 0,1
    #pragma unroll
    for (int it = 0; it < 4; it++) {
        const int idx = it * 256 + tid;
        const int row = idx >> 3, ck = idx & 7;
        cpa16(sbase + SWZ((uint32_t)(row * 128 + ck * 16)),
              Qfp + (size_t)(q0 + row) * HD_ + ck * 8);
    }
    CPA_COMMIT();
    issueKV(0, 0); issueKV(1, 1);

    CPA_WAIT(2);           // Q done
    __syncthreads();

    // Q fragments (held in registers for whole kernel)
    uint32_t qf[4][4];
    #pragma unroll
    for (int ks = 0; ks < 4; ks++) {
        const int row = wid * 16 + (lane & 15);
        const uint32_t byt = (uint32_t)(row * 128 + ks * 32 + ((lane >> 4) << 4));
        ldm_x4(qf[ks][0], qf[ks][1], qf[ks][2], qf[ks][3], sbase + SWZ(byt));
    }

    float l_acc[4] = {0.f, 0.f, 0.f, 0.f};
    float o_acc[8][4];
    #pragma unroll
    for (int i = 0; i < 8; i++)
        #pragma unroll
        for (int j = 0; j < 4; j++) o_acc[i][j] = 0.f;

    for (int kt = 0; kt < 32; kt++) {
        if (kt < 31) { CPA_WAIT(1); } else { CPA_WAIT(0); }
        __syncthreads();

        const int st = kt & 1;
        const uint32_t sKf = sbase + 16384 + st * 16384 - 16384 + 16384; // = sbase + 16384 + st*16384
        const uint32_t sK = sbase + 16384 + st * 16384;
        const uint32_t sV = sK + 8192;
        (void)sKf;

        // ---- S = Q K^T (log2-domain scores), batched ldm per ks ----
        float sc[8][4];
        #pragma unroll
        for (int i = 0; i < 8; i++)
            #pragma unroll
            for (int j = 0; j < 4; j++) sc[i][j] = 0.f;

        #pragma unroll
        for (int ks = 0; ks < 4; ks++) {
            uint32_t kf[4][4];
            #pragma unroll
            for (int ntp = 0; ntp < 4; ntp++) {
                const int row = ntp * 16 + (lane & 15);
                const uint32_t byt = (uint32_t)(row * 128 + ks * 32 + ((lane >> 4) << 4));
                ldm_x4(kf[ntp][0], kf[ntp][1], kf[ntp][2], kf[ntp][3], sK + SWZ(byt));
            }
            #pragma unroll
            for (int ntp = 0; ntp < 4; ntp++) {
                mma16816h(sc[2*ntp],   qf[ks], kf[ntp][0], kf[ntp][2]);
                mma16816h(sc[2*ntp+1], qf[ks], kf[ntp][1], kf[ntp][3]);
            }
        }

        // ---- fused softmax + PV per k-chunk, batched V ldm ----
        #pragma unroll
        for (int ks2 = 0; ks2 < 4; ks2++) {
            const int n0 = 2 * ks2, n1 = 2 * ks2 + 1;
            uint32_t vf[4][4];
            #pragma unroll
            for (int dtp = 0; dtp < 4; dtp++) {
                const int row = ks2 * 16 + (lane & 15);
                const uint32_t byt = (uint32_t)(row * 128 + dtp * 32 + ((lane >> 4) << 4));
                ldm_x4t(vf[dtp][0], vf[dtp][1], vf[dtp][2], vf[dtp][3], sV + SWZ(byt));
            }
            const float p00 = ex2(sc[n0][0]);
            const float p01 = ex2(sc[n0][1]);
            const float p02 = ex2(sc[n0][2]);
            const float p03 = ex2(sc[n0][3]);
            const float p10 = ex2(sc[n1][0]);
            const float p11 = ex2(sc[n1][1]);
            const float p12 = ex2(sc[n1][2]);
            const float p13 = ex2(sc[n1][3]);
            uint32_t aPf[4];
            aPf[0] = packh(p00, p01);
            aPf[1] = packh(p02, p03);
            aPf[2] = packh(p10, p11);
            aPf[3] = packh(p12, p13);
            mma16816h(l_acc, aPf, ONES2, ONES2);
            #pragma unroll
            for (int dtp = 0; dtp < 4; dtp++) {
                mma16816h(o_acc[2*dtp],   aPf, vf[dtp][0], vf[dtp][1]);
                mma16816h(o_acc[2*dtp+1], aPf, vf[dtp][2], vf[dtp][3]);
            }
        }
        __syncthreads();
        if (kt + 2 < 32) issueKV(kt + 2, st);
    }

    // ---- epilogue: l already full row-sum in every lane; no shuffles ----
    #pragma unroll
    for (int tr = 0; tr < 2; tr++) {
        const float inv = 1.f / l_acc[tr * 2];
        const int qrow = q0 + wid * 16 + g + tr * 8;
        #pragma unroll
        for (int dt = 0; dt < 8; dt++) {
            float2 w;
            w.x = o_acc[dt][tr*2]   * inv;
            w.y = o_acc[dt][tr*2+1] * inv;
            *(float2*)&Out[((size_t)b * S_ + qrow) * D_ + h * HD_ + dt * 8 + q2] = w;
        }
    }
}

// ---------------------------------------------------------------------------
extern "C" void kernel_launch(void* const* d_in, const int* in_sizes, int n_in,
                              void* d_out, int out_size)
{
    const float* X  = (const float*)d_in[0];
    const float* Wq = (const float*)d_in[1];
    const float* Wk = (const float*)d_in[2];
    const float* Wv = (const float*)d_in[3];
    const float* sn = (const float*)d_in[4];
    const float* cs = (const float*)d_in[5];
    float* out = (float*)d_out;

    prep_kernel<<<4096 + 3072, 256>>>(X, Wq, Wk, Wv);

    cudaFuncSetAttribute(qkv_hmma_kernel, cudaFuncAttributeMaxDynamicSharedMemorySize, QKV_SMEM);
    dim3 g1(D_ / 128, M_ / 128, 3);   // (8, 32, 3)
    qkv_hmma_kernel<<<g1, 256, QKV_SMEM>>>(sn, cs);

    cudaFuncSetAttribute(attn_hmma_kernel, cudaFuncAttributeMaxDynamicSharedMemorySize, ATT_SMEM);
    dim3 g2(S_ / 128, H_, B_);        // (16, 16, 2)
    attn_hmma_kernel<<<g2, 256, ATT_SMEM>>>(out);
}

// round 16
// speedup vs baseline: 1.0436x; 1.0138x over previous
#include <cuda_runtime.h>
#include <cuda_fp16.h>
#include <math.h>
#include <stdint.h>

#define B_  2
#define S_  2048
#define D_  1024
#define H_  16
#define HD_ 64
#define M_  (B_*S_)   // 4096

// fp16 planes for the projection GEMM
__device__ __half g_Xf[M_*D_];          // X  [m][k]
__device__ __half g_Wf[3*D_*D_];        // W  [k][n] x3 (natural layout, fp16)
// Rotated Q/K/V single fp16 planes, [B,H,S,HD]. Q pre-scaled by 0.125*log2e.
__device__ __half g_Qf[B_*H_*S_*HD_];
__device__ __half g_Kf[B_*H_*S_*HD_];
__device__ __half g_Vf[B_*H_*S_*HD_];

// ===========================================================================
// helpers
// ===========================================================================
__device__ __forceinline__ uint32_t smem_u32(const void* p) {
    uint32_t a;
    asm("{ .reg .u64 t; cvta.to.shared.u64 t, %1; cvt.u32.u64 %0, t; }" : "=r"(a) : "l"(p));
    return a;
}
#define SWZ(off) ((off) ^ (((off) >> 3) & 0x70))

__device__ __forceinline__ void cpa16(uint32_t dst, const void* src) {
    asm volatile("cp.async.cg.shared.global [%0], [%1], 16;" :: "r"(dst), "l"(src));
}
#define CPA_COMMIT() asm volatile("cp.async.commit_group;" ::: "memory")
#define CPA_WAIT(n)  asm volatile("cp.async.wait_group %0;" :: "n"(n) : "memory")

__device__ __forceinline__ void ldm_x4(uint32_t& r0, uint32_t& r1, uint32_t& r2, uint32_t& r3, uint32_t a) {
    asm volatile("ldmatrix.sync.aligned.m8n8.x4.shared.b16 {%0,%1,%2,%3}, [%4];"
                 : "=r"(r0), "=r"(r1), "=r"(r2), "=r"(r3) : "r"(a));
}
__device__ __forceinline__ void ldm_x4t(uint32_t& r0, uint32_t& r1, uint32_t& r2, uint32_t& r3, uint32_t a) {
    asm volatile("ldmatrix.sync.aligned.m8n8.x4.trans.shared.b16 {%0,%1,%2,%3}, [%4];"
                 : "=r"(r0), "=r"(r1), "=r"(r2), "=r"(r3) : "r"(a));
}
// fp16 MMA
__device__ __forceinline__ void mma16816h(float* c, const uint32_t* a, uint32_t b0, uint32_t b1) {
    asm volatile(
        "mma.sync.aligned.m16n8k16.row.col.f32.f16.f16.f32 "
        "{%0,%1,%2,%3}, {%4,%5,%6,%7}, {%8,%9}, {%0,%1,%2,%3};"
        : "+f"(c[0]), "+f"(c[1]), "+f"(c[2]), "+f"(c[3])
        : "r"(a[0]), "r"(a[1]), "r"(a[2]), "r"(a[3]), "r"(b0), "r"(b1));
}
// fp16 pack
__device__ __forceinline__ uint32_t packh(float p0, float p1) {
    uint32_t r;
    asm("cvt.rn.f16x2.f32 %0, %1, %2;" : "=r"(r) : "f"(p1), "f"(p0));
    return r;
}
__device__ __forceinline__ float ex2(float x) {
    float y; asm("ex2.approx.f32 %0, %1;" : "=f"(y) : "f"(x)); return y;
}

// ===========================================================================
// Prep: single merged kernel. Blocks [0,4096) pack X; [4096,7168) pack Ws.
// ===========================================================================
__global__ __launch_bounds__(256) void prep_kernel(
    const float* __restrict__ X,
    const float* __restrict__ Wq, const float* __restrict__ Wk, const float* __restrict__ Wv)
{
    const int blk = blockIdx.x;
    if (blk < 4096) {
        const int i = blk * 256 + threadIdx.x;            // float4 index, 1M total
        float4 v = ((const float4*)X)[i];
        ((uint32_t*)g_Xf)[i*2]   = packh(v.x, v.y);
        ((uint32_t*)g_Xf)[i*2+1] = packh(v.z, v.w);
    } else {
        const int i = (blk - 4096) * 256 + threadIdx.x;   // 0 .. 768K-1
        const int w = i >> 18;                            // 256K float4 per W
        const int j = i & 0x3FFFF;
        const float* W = (w == 0) ? Wq : (w == 1 ? Wk : Wv);
        float4 v = ((const float4*)W)[j];
        uint32_t* O = (uint32_t*)(g_Wf + (size_t)w * D_ * D_);
        O[j*2]   = packh(v.x, v.y);
        O[j*2+1] = packh(v.z, v.w);
    }
}

// ===========================================================================
// Kernel 1: QKV GEMM, fp16, tile 128x128, BK=64, cp.async 2-stage.
//   (unchanged from R15)
// ===========================================================================
#define QKV_STAGE 32768
#define QKV_SMEM (2 * QKV_STAGE)
#define LOG2E 1.44269504088896340736f

__global__ __launch_bounds__(256, 2)
void qkv_hmma_kernel(const float* __restrict__ sinT, const float* __restrict__ cosT)
{
    extern __shared__ char smem[];
    const uint32_t sbase = smem_u32(smem);
    const int tid = threadIdx.x;
    const int wid = tid >> 5;
    const int lane = tid & 31;
    const int wm = (wid >> 1) * 32;    // 0,32,64,96
    const int wp = (wid & 1);          // B plane 0/1 -> n offset 0/64

    const int which = blockIdx.z;
    const int bm = blockIdx.y * 128;
    const int bn = blockIdx.x * 128;
    const __half* Wp = g_Wf + (size_t)which * D_ * D_;
    __half* Outp = (which == 0) ? g_Qf : (which == 1 ? g_Kf : g_Vf);
    const float qscale = (which == 0) ? (0.125f * LOG2E) : 1.0f;

    // precomputed per-thread load offsets (invariant across chunks)
    uint32_t a_dst[4]; const __half* a_src[4];
    #pragma unroll
    for (int it = 0; it < 4; it++) {
        const int idx = it * 256 + tid;
        const int row = idx >> 3, ck = idx & 7;
        a_dst[it] = SWZ((uint32_t)(row * 128 + ck * 16));
        a_src[it] = g_Xf + (size_t)(bm + row) * D_ + ck * 8;
    }
    uint32_t b_dst[2][2]; const __half* b_src[2][2];
    #pragma unroll
    for (int p = 0; p < 2; p++)
        #pragma unroll
        for (int it = 0; it < 2; it++) {
            const int idx = it * 256 + tid;
            const int row = idx >> 3, ck = idx & 7;
            b_dst[p][it] = 16384 + p * 8192 + SWZ((uint32_t)(row * 128 + ck * 16));
            b_src[p][it] = Wp + (size_t)row * D_ + bn + p * 64 + ck * 8;
        }

    auto issue = [&](int ch, int st) {
        const uint32_t sb = sbase + st * QKV_STAGE;
        #pragma unroll
        for (int it = 0; it < 4; it++)
            cpa16(sb + a_dst[it], a_src[it] + ch * 64);
        #pragma unroll
        for (int p = 0; p < 2; p++)
            #pragma unroll
            for (int it = 0; it < 2; it++)
                cpa16(sb + b_dst[p][it], b_src[p][it] + (size_t)(ch * 64) * D_);
        CPA_COMMIT();
    };

    float acc[2][8][4];
    #pragma unroll
    for (int i = 0; i < 2; i++)
        #pragma unroll
        for (int j = 0; j < 8; j++)
            #pragma unroll
            for (int k = 0; k < 4; k++) acc[i][j][k] = 0.f;

    issue(0, 0); issue(1, 1);

    for (int ch = 0; ch < 16; ch++) {
        if (ch < 15) { CPA_WAIT(1); } else { CPA_WAIT(0); }
        __syncthreads();

        const int st = ch & 1;
        const uint32_t sA = sbase + st * QKV_STAGE;
        const uint32_t sB = sA + 16384 + wp * 8192;

        #pragma unroll
        for (int ks = 0; ks < 4; ks++) {
            uint32_t af[2][4];
            #pragma unroll
            for (int mt = 0; mt < 2; mt++) {
                const int row = wm + mt * 16 + (lane & 15);
                const uint32_t byt = (uint32_t)(row * 128 + ks * 32 + ((lane >> 4) << 4));
                ldm_x4(af[mt][0], af[mt][1], af[mt][2], af[mt][3], sA + SWZ(byt));
            }
            uint32_t bf[4][4];
            #pragma unroll
            for (int ntq = 0; ntq < 4; ntq++) {
                const int row = ks * 16 + (lane & 15);
                const uint32_t byt = (uint32_t)(row * 128 + ntq * 32 + ((lane >> 4) << 4));
                ldm_x4t(bf[ntq][0], bf[ntq][1], bf[ntq][2], bf[ntq][3], sB + SWZ(byt));
            }
            #pragma unroll
            for (int ntq = 0; ntq < 4; ntq++)
                #pragma unroll
                for (int mt = 0; mt < 2; mt++) {
                    mma16816h(acc[mt][2*ntq],   af[mt], bf[ntq][0], bf[ntq][1]);
                    mma16816h(acc[mt][2*ntq+1], af[mt], bf[ntq][2], bf[ntq][3]);
                }
        }
        __syncthreads();
        if (ch + 2 < 16) issue(ch + 2, st);
    }

    // epilogue: RoPE + scale, pack to single fp16 plane
    const int g = lane >> 2;
    const int q2 = (lane & 3) * 2;
    #pragma unroll
    for (int mt = 0; mt < 2; mt++) {
        #pragma unroll
        for (int rr = 0; rr < 2; rr++) {
            const int row = bm + wm + mt * 16 + g + rr * 8;
            const int bb = row >> 11;
            const int ss = row & 2047;
            #pragma unroll
            for (int nt = 0; nt < 8; nt++) {
                const int c = bn + wp * 64 + nt * 8 + q2;
                const int h = c >> 6;
                const int d = c & 63;
                const float sn = sinT[ss * (HD_/2) + (d >> 1)];
                const float cs = cosT[ss * (HD_/2) + (d >> 1)];
                const float e = acc[mt][nt][rr * 2 + 0];
                const float o = acc[mt][nt][rr * 2 + 1];
                const float wx = (e * cs - o * sn) * qscale;
                const float wy = (o * cs + e * sn) * qscale;
                const size_t ob = ((size_t)(bb * H_ + h) * S_ + ss) * HD_ + d;
                *(uint32_t*)&Outp[ob] = packh(wx, wy);
            }
        }
    }
}

// ===========================================================================
// Kernel 2: flash attention, fp16 single-plane, PAIRED KV tiles.
//   BQ=128 (8 warps x 16 rows). Super-stage = 2 KV tiles (32KB), 2 super-
//   stages in ring (64KB) + Q 16KB = 80KB -> 2 CTAs/SM. One barrier + one
//   commit per 2 tiles (16 barriers total instead of 32).
// ===========================================================================
#define ATT_SSTAGE 32768
#define ATT_SMEM (16384 + 2 * ATT_SSTAGE)
#define ONES2 0x3C003C00u    // fp16x2 (1.0, 1.0)

__global__ __launch_bounds__(256, 2)
void attn_hmma_kernel(float* __restrict__ Out)
{
    extern __shared__ char smem[];
    const uint32_t sbase = smem_u32(smem);
    const int tid = threadIdx.x;
    const int wid = tid >> 5;
    const int lane = tid & 31;
    const int g = lane >> 2;
    const int q2 = (lane & 3) * 2;

    const int q0 = blockIdx.x * 128;
    const int h  = blockIdx.y;
    const int b  = blockIdx.z;
    const size_t hoff = (size_t)(b * H_ + h) * S_ * HD_;
    const __half* Qfp = g_Qf + hoff;

    // precomputed per-thread KV load offsets (within one 16KB sub-tile)
    uint32_t kv_dst[2][2]; const __half* kv_src[2][2];
    {
        const __half* planes[2] = {g_Kf + hoff, g_Vf + hoff};
        #pragma unroll
        for (int p = 0; p < 2; p++)
            #pragma unroll
            for (int it = 0; it < 2; it++) {
                const int idx = it * 256 + tid;    // 512 per plane
                const int row = idx >> 3, ck = idx & 7;
                kv_dst[p][it] = p * 8192 + SWZ((uint32_t)(row * 128 + ck * 16));
                kv_src[p][it] = planes[p] + (size_t)row * HD_ + ck * 8;
            }
    }

    // issue a PAIR of KV tiles (2*kp, 2*kp+1) into super-stage st; one commit
    auto issuePair = [&](int kp, int st) {
        const uint32_t sb = sbase + 16384 + st * ATT_SSTAGE;
        #pragma unroll
        for (int sub = 0; sub < 2; sub++) {
            const int roff = (kp * 2 + sub) * 64 * HD_;
            const uint32_t so = sb + sub * 16384;
            #pragma unroll
            for (int p = 0; p < 2; p++)
                #pragma unroll
                for (int it = 0; it < 2; it++)
                    cpa16(so + kv_dst[p][it], kv_src[p][it] + roff);
        }
        CPA_COMMIT();
    };

    // prologue: Q (single plane) + KV pairs 0,1
    #pragma unroll
    for (int it = 0; it < 4; it++) {
        const int idx = it * 256 + tid;
        const int row = idx >> 3, ck = idx & 7;
        cpa16(sbase + SWZ((uint32_t)(row * 128 + ck * 16)),
              Qfp + (size_t)(q0 + row) * HD_ + ck * 8);
    }
    CPA_COMMIT();
    issuePair(0, 0); issuePair(1, 1);

    CPA_WAIT(2);           // Q done
    __syncthreads();

    // Q fragments (held in registers for whole kernel)
    uint32_t qf[4][4];
    #pragma unroll
    for (int ks = 0; ks < 4; ks++) {
        const int row = wid * 16 + (lane & 15);
        const uint32_t byt = (uint32_t)(row * 128 + ks * 32 + ((lane >> 4) << 4));
        ldm_x4(qf[ks][0], qf[ks][1], qf[ks][2], qf[ks][3], sbase + SWZ(byt));
    }

    float l_acc[4] = {0.f, 0.f, 0.f, 0.f};
    float o_acc[8][4];
    #pragma unroll
    for (int i = 0; i < 8; i++)
        #pragma unroll
        for (int j = 0; j < 4; j++) o_acc[i][j] = 0.f;

    for (int kp = 0; kp < 16; kp++) {          // 16 super-iterations, 2 tiles each
        if (kp < 15) { CPA_WAIT(1); } else { CPA_WAIT(0); }
        __syncthreads();

        const int st = kp & 1;
        const uint32_t sstage = sbase + 16384 + st * ATT_SSTAGE;

        #pragma unroll
        for (int sub = 0; sub < 2; sub++) {
            const uint32_t sK = sstage + sub * 16384;
            const uint32_t sV = sK + 8192;

            // ---- S = Q K^T (log2-domain scores), batched ldm per ks ----
            float sc[8][4];
            #pragma unroll
            for (int i = 0; i < 8; i++)
                #pragma unroll
                for (int j = 0; j < 4; j++) sc[i][j] = 0.f;

            #pragma unroll
            for (int ks = 0; ks < 4; ks++) {
                uint32_t kf[4][4];
                #pragma unroll
                for (int ntp = 0; ntp < 4; ntp++) {
                    const int row = ntp * 16 + (lane & 15);
                    const uint32_t byt = (uint32_t)(row * 128 + ks * 32 + ((lane >> 4) << 4));
                    ldm_x4(kf[ntp][0], kf[ntp][1], kf[ntp][2], kf[ntp][3], sK + SWZ(byt));
                }
                #pragma unroll
                for (int ntp = 0; ntp < 4; ntp++) {
                    mma16816h(sc[2*ntp],   qf[ks], kf[ntp][0], kf[ntp][2]);
                    mma16816h(sc[2*ntp+1], qf[ks], kf[ntp][1], kf[ntp][3]);
                }
            }

            // ---- fused softmax + PV per k-chunk, batched V ldm ----
            #pragma unroll
            for (int ks2 = 0; ks2 < 4; ks2++) {
                const int n0 = 2 * ks2, n1 = 2 * ks2 + 1;
                uint32_t vf[4][4];
                #pragma unroll
                for (int dtp = 0; dtp < 4; dtp++) {
                    const int row = ks2 * 16 + (lane & 15);
                    const uint32_t byt = (uint32_t)(row * 128 + dtp * 32 + ((lane >> 4) << 4));
                    ldm_x4t(vf[dtp][0], vf[dtp][1], vf[dtp][2], vf[dtp][3], sV + SWZ(byt));
                }
                const float p00 = ex2(sc[n0][0]);
                const float p01 = ex2(sc[n0][1]);
                const float p02 = ex2(sc[n0][2]);
                const float p03 = ex2(sc[n0][3]);
                const float p10 = ex2(sc[n1][0]);
                const float p11 = ex2(sc[n1][1]);
                const float p12 = ex2(sc[n1][2]);
                const float p13 = ex2(sc[n1][3]);
                uint32_t aPf[4];
                aPf[0] = packh(p00, p01);
                aPf[1] = packh(p02, p03);
                aPf[2] = packh(p10, p11);
                aPf[3] = packh(p12, p13);
                mma16816h(l_acc, aPf, ONES2, ONES2);
                #pragma unroll
                for (int dtp = 0; dtp < 4; dtp++) {
                    mma16816h(o_acc[2*dtp],   aPf, vf[dtp][0], vf[dtp][1]);
                    mma16816h(o_acc[2*dtp+1], aPf, vf[dtp][2], vf[dtp][3]);
                }
            }
        }
        __syncthreads();
        if (kp + 2 < 16) issuePair(kp + 2, st);
    }

    // ---- epilogue: l already full row-sum in every lane; no shuffles ----
    #pragma unroll
    for (int tr = 0; tr < 2; tr++) {
        const float inv = 1.f / l_acc[tr * 2];
        const int qrow = q0 + wid * 16 + g + tr * 8;
        #pragma unroll
        for (int dt = 0; dt < 8; dt++) {
            float2 w;
            w.x = o_acc[dt][tr*2]   * inv;
            w.y = o_acc[dt][tr*2+1] * inv;
            *(float2*)&Out[((size_t)b * S_ + qrow) * D_ + h * HD_ + dt * 8 + q2] = w;
        }
    }
}

// ---------------------------------------------------------------------------
extern "C" void kernel_launch(void* const* d_in, const int* in_sizes, int n_in,
                              void* d_out, int out_size)
{
    const float* X  = (const float*)d_in[0];
    const float* Wq = (const float*)d_in[1];
    const float* Wk = (const float*)d_in[2];
    const float* Wv = (const float*)d_in[3];
    const float* sn = (const float*)d_in[4];
    const float* cs = (const float*)d_in[5];
    float* out = (float*)d_out;

    prep_kernel<<<4096 + 3072, 256>>>(X, Wq, Wk, Wv);

    cudaFuncSetAttribute(qkv_hmma_kernel, cudaFuncAttributeMaxDynamicSharedMemorySize, QKV_SMEM);
    dim3 g1(D_ / 128, M_ / 128, 3);   // (8, 32, 3)
    qkv_hmma_kernel<<<g1, 256, QKV_SMEM>>>(sn, cs);

    cudaFuncSetAttribute(attn_hmma_kernel, cudaFuncAttributeMaxDynamicSharedMemorySize, ATT_SMEM);
    dim3 g2(S_ / 128, H_, B_);        // (16, 16, 2)
    attn_hmma_kernel<<<g2, 256, ATT_SMEM>>>(out);
}